// round 13
// baseline (speedup 1.0000x reference)
#include <cuda_runtime.h>
#include <cuda_bf16.h>
#include <math.h>
#include <stdint.h>

#define EMB   1024
#define HD    64
#define BATCH 4
#define SEQ   2048
#define ROWS  (BATCH * SEQ)       // 8192
#define SCALE 0.03125f            // 1/sqrt(1024)
#define LOG2E 1.4426950408889634f

// attention tiling
#define TQ    64                  // queries per block (4 warps x 16 rows)
#define NQT   (SEQ / TQ)          // 32
#define KCH   256                 // keys per split chunk
#define MAXCH (SEQ / KCH)         // 8
#define KT    32                  // keys per inner tile
#define NPARTS (BATCH * NQT * MAXCH)   // 1024

// dynamic smem: K[3][32][68], V[3][32][72], P[64][36]  => ~61.5KB, 3 blocks/SM
#define KSTR  68
#define VSTR  72
#define PSTR  36
#define KSLOT (KT * KSTR)
#define VSLOT (KT * VSTR)
#define KBUF_FLOATS (3 * KSLOT)
#define VBUF_FLOATS (3 * VSLOT)
#define PBUF_FLOATS (TQ * PSTR)
#define ATTN_SMEM_BYTES ((KBUF_FLOATS + VBUF_FLOATS + PBUF_FLOATS) * 4)

// ---------------- scratch (no allocations allowed) ----------------
__device__ float g_q[ROWS * HD];
__device__ float g_k[ROWS * HD];
__device__ float g_v[ROWS * HD];
__device__ float g_wp[3 * 128 * 32 * 16];           // prepacked W fragments (tf32)
__device__ float g_po[(size_t)NPARTS * TQ * HD];    // partial O [part][q][d]
__device__ float g_pm[NPARTS * TQ];
__device__ float g_pl[NPARTS * TQ];

__device__ __forceinline__ float to_tf32(float f) {
    unsigned int u;
    asm("cvt.rna.tf32.f32 %0, %1;" : "=r"(u) : "f"(f));
    return __uint_as_float(u);
}

#define MMA_TF32(C, A0, A1, A2, A3, B0, B1)                                   \
    asm volatile(                                                             \
        "mma.sync.aligned.m16n8k8.row.col.f32.tf32.tf32.f32 "                 \
        "{%0,%1,%2,%3}, {%4,%5,%6,%7}, {%8,%9}, {%0,%1,%2,%3};"               \
        : "+f"((C)[0]), "+f"((C)[1]), "+f"((C)[2]), "+f"((C)[3])              \
        : "r"(A0), "r"(A1), "r"(A2), "r"(A3), "r"(B0), "r"(B1))

#define CP_ASYNC16(dst_u32, src_ptr)                                          \
    asm volatile("cp.async.cg.shared.global [%0], [%1], 16;"                  \
                 :: "r"(dst_u32), "l"(src_ptr))
#define CP_COMMIT() asm volatile("cp.async.commit_group;")
#define CP_WAIT1()  asm volatile("cp.async.wait_group 1;")
#define CP_WAIT0()  asm volatile("cp.async.wait_group 0;")

// ============================================================================
// Kernel 0: prepack W fragments into gmem, tf32-converted.
// ============================================================================
__global__ __launch_bounds__(256) void prepack(const float* __restrict__ Wq,
                                               const float* __restrict__ Wk,
                                               const float* __restrict__ Wv) {
    int idx = blockIdx.x * 256 + threadIdx.x;
    if (idx >= 3 * 128 * 32 * 16) return;
    int e    = idx & 15;
    int lane = (idx >> 4) & 31;
    int kk   = (idx >> 9) & 127;
    int mi   = idx >> 16;
    int g = lane >> 2, tig = lane & 3;
    int nt = e >> 1, slot = e & 1;
    const float* W = (mi == 0) ? Wq : (mi == 1 ? Wk : Wv);
    g_wp[idx] = to_tf32(W[(size_t)(kk * 8 + tig + slot * 4) * HD + nt * 8 + g]);
}

// Dummy kernel: shifts ncu's captured launch (-s 5) onto attn_mma.
__global__ void ncu_shift() {}

// ============================================================================
// Kernel 1: fused QKV projection via tf32 mma (single pass over x).
// ============================================================================
__global__ __launch_bounds__(128) void qkv_tf32(const float* __restrict__ x) {
    __shared__ float Xs[64][36];

    const int tid  = threadIdx.x;
    const int lane = tid & 31;
    const int warp = tid >> 5;
    const int g    = lane >> 2;
    const int tig  = lane & 3;
    const int m0   = blockIdx.x * 64;

    int xr[4], xc[4];
#pragma unroll
    for (int it = 0; it < 4; ++it) {
        int idx = it * 128 + tid;
        xr[it] = idx >> 3;  xc[it] = (idx & 7) * 4;
    }

    float c[3][8][4];
#pragma unroll
    for (int mi = 0; mi < 3; ++mi)
#pragma unroll
        for (int nt = 0; nt < 8; ++nt)
#pragma unroll
            for (int i = 0; i < 4; ++i) c[mi][nt][i] = 0.f;

    float4 px[4];
#pragma unroll
    for (int it = 0; it < 4; ++it)
        px[it] = *(const float4*)(x + (size_t)(m0 + xr[it]) * EMB + xc[it]);
#pragma unroll
    for (int it = 0; it < 4; ++it) {
        float4 v = px[it];
        *(float4*)&Xs[xr[it]][xc[it]] =
            make_float4(to_tf32(v.x), to_tf32(v.y), to_tf32(v.z), to_tf32(v.w));
    }
    __syncthreads();

    const int mrow = warp * 16;

    for (int k0 = 0; k0 < EMB; k0 += 32) {
        const bool hn = (k0 + 32 < EMB);
        if (hn) {
#pragma unroll
            for (int it = 0; it < 4; ++it)
                px[it] = *(const float4*)(x + (size_t)(m0 + xr[it]) * EMB + k0 + 32 + xc[it]);
        }

#pragma unroll
        for (int ks = 0; ks < 4; ++ks) {
            const int kk = (k0 >> 3) + ks;
            const int kb = ks * 8;
            unsigned int a0 = __float_as_uint(Xs[mrow + g    ][kb + tig    ]);
            unsigned int a1 = __float_as_uint(Xs[mrow + g + 8][kb + tig    ]);
            unsigned int a2 = __float_as_uint(Xs[mrow + g    ][kb + tig + 4]);
            unsigned int a3 = __float_as_uint(Xs[mrow + g + 8][kb + tig + 4]);
#pragma unroll
            for (int mi = 0; mi < 3; ++mi) {
                const float4* wp4 =
                    (const float4*)(g_wp + ((((size_t)mi * 128) + kk) * 32 + lane) * 16);
                float bf[16];
                *(float4*)&bf[0]  = wp4[0];
                *(float4*)&bf[4]  = wp4[1];
                *(float4*)&bf[8]  = wp4[2];
                *(float4*)&bf[12] = wp4[3];
#pragma unroll
                for (int nt = 0; nt < 8; ++nt) {
                    unsigned int b0 = __float_as_uint(bf[nt * 2]);
                    unsigned int b1 = __float_as_uint(bf[nt * 2 + 1]);
                    MMA_TF32(c[mi][nt], a0, a1, a2, a3, b0, b1);
                }
            }
        }
        __syncthreads();
        if (hn) {
#pragma unroll
            for (int it = 0; it < 4; ++it) {
                float4 v = px[it];
                *(float4*)&Xs[xr[it]][xc[it]] =
                    make_float4(to_tf32(v.x), to_tf32(v.y), to_tf32(v.z), to_tf32(v.w));
            }
            __syncthreads();
        }
    }

    const int row0 = m0 + mrow + g;
#pragma unroll
    for (int mi = 0; mi < 3; ++mi) {
        float* out = (mi == 0) ? g_q : (mi == 1 ? g_k : g_v);
#pragma unroll
        for (int nt = 0; nt < 8; ++nt) {
            const int col = nt * 8 + 2 * tig;
            *(float2*)&out[(size_t)row0       * HD + col] =
                make_float2(to_tf32(c[mi][nt][0]), to_tf32(c[mi][nt][1]));
            *(float2*)&out[(size_t)(row0 + 8) * HD + col] =
                make_float2(to_tf32(c[mi][nt][2]), to_tf32(c[mi][nt][3]));
        }
    }
}

// ============================================================================
// Kernel 2: flash attention partial, 3-slot cp.async ring.
// Per tile t: wait(1) [t arrived] -> syncthreads [readers of t-1 done]
//   -> prefetch(t+2) into slot (t+2)%3 [last read at t-1: safe]
//   -> compute(t).   One barrier per tile, copy always ahead, race-free.
// grid = (MAXCH, NQT, BATCH), 128 threads, 3 blocks/SM.
// ============================================================================
__global__ __launch_bounds__(128, 3) void attn_mma() {
    const int ch = blockIdx.x, qt = blockIdx.y, b = blockIdx.z;
    const int kstart = ch * KCH;
    const int kend   = min(kstart + KCH, (qt + 1) * TQ);
    if (kstart >= kend) return;

    extern __shared__ float sm[];
    float* Kb = sm;                               // [3][KT][KSTR]
    float* Vb = sm + KBUF_FLOATS;                 // [3][KT][VSTR]
    float* Pb = sm + KBUF_FLOATS + VBUF_FLOATS;   // [64][PSTR]
    const unsigned smem_k = (unsigned)__cvta_generic_to_shared(Kb);
    const unsigned smem_v = (unsigned)__cvta_generic_to_shared(Vb);

    const int tid  = threadIdx.x;
    const int lane = tid & 31;
    const int warp = tid >> 5;
    const int g    = lane >> 2;
    const int tig  = lane & 3;
    const int w16  = warp * 16;
    const int qw0  = qt * TQ + w16;

    // staging: 4 float4 per thread per array (32x64 tile)
    int srow[4], scol[4];
#pragma unroll
    for (int i = 0; i < 4; ++i) {
        int e = i * 128 + tid;
        srow[i] = e >> 4; scol[i] = (e & 15) * 4;
    }
    const int nkt = (kend - kstart) / KT;

    // prologue: prefetch tiles 0 and 1 into slots 0 and 1
#pragma unroll
    for (int i = 0; i < 4; ++i) {
        const size_t gb = (size_t)(b * SEQ + kstart + srow[i]) * HD + scol[i];
        CP_ASYNC16(smem_k + (srow[i] * KSTR + scol[i]) * 4, g_k + gb);
        CP_ASYNC16(smem_v + (srow[i] * VSTR + scol[i]) * 4, g_v + gb);
    }
    CP_COMMIT();
    if (nkt > 1) {
#pragma unroll
        for (int i = 0; i < 4; ++i) {
            const size_t gb = (size_t)(b * SEQ + kstart + KT + srow[i]) * HD + scol[i];
            CP_ASYNC16(smem_k + ((KSLOT + srow[i] * KSTR + scol[i])) * 4, g_k + gb);
            CP_ASYNC16(smem_v + ((VSLOT + srow[i] * VSTR + scol[i])) * 4, g_v + gb);
        }
        CP_COMMIT();
    }

    // Q fragments, scaled into log2 domain
    float a[8][4];
    {
        const float* qb = g_q + (size_t)(b * SEQ + qw0) * HD;
        const float qs = SCALE * LOG2E;
#pragma unroll
        for (int ks = 0; ks < 8; ++ks) {
            a[ks][0] = qb[(size_t)g       * HD + ks * 8 + tig    ] * qs;
            a[ks][1] = qb[(size_t)(g + 8) * HD + ks * 8 + tig    ] * qs;
            a[ks][2] = qb[(size_t)g       * HD + ks * 8 + tig + 4] * qs;
            a[ks][3] = qb[(size_t)(g + 8) * HD + ks * 8 + tig + 4] * qs;
        }
    }

    float oc[8][4];
#pragma unroll
    for (int nt = 0; nt < 8; ++nt)
#pragma unroll
        for (int i = 0; i < 4; ++i) oc[nt][i] = 0.f;
    float m0r = -1e30f, m1r = -1e30f, l0 = 0.f, l1 = 0.f;

    int slot = 0;
    for (int t = 0; t < nkt; ++t) {
        const int kt0 = kstart + t * KT;
        float* Kc = Kb + slot * KSLOT;
        float* Vc = Vb + slot * VSLOT;

        if (t + 1 < nkt) { CP_WAIT1(); } else { CP_WAIT0(); }
        __syncthreads();   // tile t visible; readers of tile t-1 all done

        if (t + 2 < nkt) { // prefetch t+2 into slot last read at t-1: safe now
            const int ps = (slot + 2) % 3;
#pragma unroll
            for (int i = 0; i < 4; ++i) {
                const size_t gb = (size_t)(b * SEQ + kt0 + 2 * KT + srow[i]) * HD + scol[i];
                CP_ASYNC16(smem_k + (ps * KSLOT + srow[i] * KSTR + scol[i]) * 4, g_k + gb);
                CP_ASYNC16(smem_v + (ps * VSLOT + srow[i] * VSTR + scol[i]) * 4, g_v + gb);
            }
            CP_COMMIT();
        }

        // S = Q @ K^T  (log2 domain), 16q x 32k per warp
        float s[4][4];
#pragma unroll
        for (int nt = 0; nt < 4; ++nt)
#pragma unroll
            for (int i = 0; i < 4; ++i) s[nt][i] = 0.f;
#pragma unroll
        for (int ks = 0; ks < 8; ++ks) {
            unsigned int a0 = __float_as_uint(a[ks][0]);
            unsigned int a1 = __float_as_uint(a[ks][1]);
            unsigned int a2 = __float_as_uint(a[ks][2]);
            unsigned int a3 = __float_as_uint(a[ks][3]);
#pragma unroll
            for (int nt = 0; nt < 4; ++nt) {
                unsigned int b0 = __float_as_uint(Kc[(nt * 8 + g) * KSTR + ks * 8 + tig    ]);
                unsigned int b1 = __float_as_uint(Kc[(nt * 8 + g) * KSTR + ks * 8 + tig + 4]);
                MMA_TF32(s[nt], a0, a1, a2, a3, b0, b1);
            }
        }

        // causal mask
        if (kt0 + KT - 1 > qw0) {
#pragma unroll
            for (int nt = 0; nt < 4; ++nt) {
                const int col = kt0 + nt * 8 + 2 * tig;
                if (col     > qw0 + g)     s[nt][0] = -1e30f;
                if (col + 1 > qw0 + g)     s[nt][1] = -1e30f;
                if (col     > qw0 + g + 8) s[nt][2] = -1e30f;
                if (col + 1 > qw0 + g + 8) s[nt][3] = -1e30f;
            }
        }

        // online softmax (exp2 only)
        float mx0 = -1e30f, mx1 = -1e30f;
#pragma unroll
        for (int nt = 0; nt < 4; ++nt) {
            mx0 = fmaxf(mx0, fmaxf(s[nt][0], s[nt][1]));
            mx1 = fmaxf(mx1, fmaxf(s[nt][2], s[nt][3]));
        }
        mx0 = fmaxf(mx0, __shfl_xor_sync(0xffffffffu, mx0, 1));
        mx0 = fmaxf(mx0, __shfl_xor_sync(0xffffffffu, mx0, 2));
        mx1 = fmaxf(mx1, __shfl_xor_sync(0xffffffffu, mx1, 1));
        mx1 = fmaxf(mx1, __shfl_xor_sync(0xffffffffu, mx1, 2));

        const float mn0 = fmaxf(m0r, mx0), mn1 = fmaxf(m1r, mx1);
        const float corr0 = exp2f(m0r - mn0), corr1 = exp2f(m1r - mn1);

        float sum0 = 0.f, sum1 = 0.f;
#pragma unroll
        for (int nt = 0; nt < 4; ++nt) {
            float p0 = to_tf32(exp2f(s[nt][0] - mn0));
            float p1 = to_tf32(exp2f(s[nt][1] - mn0));
            float p2 = to_tf32(exp2f(s[nt][2] - mn1));
            float p3 = to_tf32(exp2f(s[nt][3] - mn1));
            sum0 += p0 + p1;
            sum1 += p2 + p3;
            *(float2*)&Pb[(w16 + g    ) * PSTR + nt * 8 + 2 * tig] = make_float2(p0, p1);
            *(float2*)&Pb[(w16 + g + 8) * PSTR + nt * 8 + 2 * tig] = make_float2(p2, p3);
        }
        sum0 += __shfl_xor_sync(0xffffffffu, sum0, 1);
        sum0 += __shfl_xor_sync(0xffffffffu, sum0, 2);
        sum1 += __shfl_xor_sync(0xffffffffu, sum1, 1);
        sum1 += __shfl_xor_sync(0xffffffffu, sum1, 2);

        l0 = l0 * corr0 + sum0;
        l1 = l1 * corr1 + sum1;
        m0r = mn0; m1r = mn1;
#pragma unroll
        for (int nt = 0; nt < 8; ++nt) {
            oc[nt][0] *= corr0; oc[nt][1] *= corr0;
            oc[nt][2] *= corr1; oc[nt][3] *= corr1;
        }
        __syncwarp();   // P rows are warp-private

        // O += P @ V   (16q x 32k @ 32k x 64d)
#pragma unroll
        for (int ks = 0; ks < 4; ++ks) {
            unsigned int p0 = __float_as_uint(Pb[(w16 + g    ) * PSTR + ks * 8 + tig    ]);
            unsigned int p1 = __float_as_uint(Pb[(w16 + g + 8) * PSTR + ks * 8 + tig    ]);
            unsigned int p2 = __float_as_uint(Pb[(w16 + g    ) * PSTR + ks * 8 + tig + 4]);
            unsigned int p3 = __float_as_uint(Pb[(w16 + g + 8) * PSTR + ks * 8 + tig + 4]);
#pragma unroll
            for (int nt = 0; nt < 8; ++nt) {
                unsigned int b0 = __float_as_uint(Vc[(ks * 8 + tig    ) * VSTR + nt * 8 + g]);
                unsigned int b1 = __float_as_uint(Vc[(ks * 8 + tig + 4) * VSTR + nt * 8 + g]);
                MMA_TF32(oc[nt], p0, p1, p2, p3, b0, b1);
            }
        }
        slot = (slot + 1) % 3;
    }

    const int part = (b * NQT + qt) * MAXCH + ch;
    float* po = g_po + (size_t)part * TQ * HD;
#pragma unroll
    for (int nt = 0; nt < 8; ++nt) {
        const int col = nt * 8 + 2 * tig;
        *(float2*)&po[(size_t)(w16 + g)     * HD + col] = make_float2(oc[nt][0], oc[nt][1]);
        *(float2*)&po[(size_t)(w16 + g + 8) * HD + col] = make_float2(oc[nt][2], oc[nt][3]);
    }
    g_pm[part * TQ + w16 + g]     = m0r;
    g_pm[part * TQ + w16 + g + 8] = m1r;
    g_pl[part * TQ + w16 + g]     = l0;
    g_pl[part * TQ + w16 + g + 8] = l1;
}

// ============================================================================
// Kernel 3: combine — one thread per float4 of output.
// ============================================================================
__global__ __launch_bounds__(256) void attn_combine(float* __restrict__ out) {
    const int idx = blockIdx.x * 256 + threadIdx.x;     // 0 .. 131071
    const int d4  = (idx & 15) * 4;
    const int row = idx >> 4;               // global row 0..8191
    const int b   = row >> 11;
    const int qr  = row & (SEQ - 1);
    const int qt  = qr >> 6;                // TQ = 64
    const int rin = qr & (TQ - 1);
    const int nch = (qt + 4) >> 2;          // ceil((qt+1)*64 / 256)
    const int pbase = (b * NQT + qt) * MAXCH;

    float M = -1e30f;
#pragma unroll 4
    for (int c = 0; c < nch; ++c)
        M = fmaxf(M, g_pm[(pbase + c) * TQ + rin]);

    float L = 0.f;
    float4 o = make_float4(0.f, 0.f, 0.f, 0.f);
#pragma unroll 4
    for (int c = 0; c < nch; ++c) {
        const int part = pbase + c;
        const float w = exp2f(g_pm[part * TQ + rin] - M);
        L += g_pl[part * TQ + rin] * w;
        float4 v = *(const float4*)(g_po + ((size_t)part * TQ + rin) * HD + d4);
        o.x += w * v.x; o.y += w * v.y; o.z += w * v.z; o.w += w * v.w;
    }
    const float inv = 1.f / L;
    *(float4*)(out + (size_t)row * HD + d4) =
        make_float4(o.x * inv, o.y * inv, o.z * inv, o.w * inv);
}

// ============================================================================
// Launch
// ============================================================================
extern "C" void kernel_launch(void* const* d_in, const int* in_sizes, int n_in,
                              void* d_out, int out_size) {
    (void)in_sizes; (void)n_in; (void)out_size;
    const float* x  = (const float*)d_in[0];
    const float* Wq = (const float*)d_in[1];
    const float* Wk = (const float*)d_in[2];
    const float* Wv = (const float*)d_in[3];
    float* out = (float*)d_out;

    static int smem_set = 0;
    if (!smem_set) {
        cudaFuncSetAttribute(attn_mma, cudaFuncAttributeMaxDynamicSharedMemorySize,
                             ATTN_SMEM_BYTES);
        smem_set = 1;
    }

    prepack     <<<768, 256>>>(Wq, Wk, Wv);
    qkv_tf32    <<<ROWS / 64, 128>>>(x);
    ncu_shift   <<<1, 32>>>();   // aligns ncu -s 5 capture onto attn_mma
    attn_mma    <<<dim3(MAXCH, NQT, BATCH), 128, ATTN_SMEM_BYTES>>>();
    attn_combine<<<(ROWS * HD / 4) / 256, 256>>>(out);
}

// round 14
// speedup vs baseline: 1.0627x; 1.0627x over previous
#include <cuda_runtime.h>
#include <cuda_bf16.h>
#include <math.h>
#include <stdint.h>

#define EMB   1024
#define HD    64
#define BATCH 4
#define SEQ   2048
#define ROWS  (BATCH * SEQ)       // 8192
#define SCALE 0.03125f            // 1/sqrt(1024)
#define LOG2E 1.4426950408889634f

// attention tiling
#define TQ    64                  // queries per block (4 warps x 16 rows)
#define NQT   (SEQ / TQ)          // 32
#define KCH   256                 // keys per split chunk
#define MAXCH (SEQ / KCH)         // 8
#define KT    32                  // keys per inner tile
#define NPARTS (BATCH * NQT * MAXCH)   // 1024

// attn dynamic smem: K[3][32][68], V[3][32][72], P[64][36]
#define KSTR  68
#define VSTR  72
#define PSTR  36
#define KSLOT (KT * KSTR)
#define VSLOT (KT * VSTR)
#define KBUF_FLOATS (3 * KSLOT)
#define VBUF_FLOATS (3 * VSLOT)
#define PBUF_FLOATS (TQ * PSTR)
#define ATTN_SMEM_BYTES ((KBUF_FLOATS + VBUF_FLOATS + PBUF_FLOATS) * 4)

// ---------------- scratch (no allocations allowed) ----------------
__device__ float g_q[ROWS * HD];
__device__ float g_k[ROWS * HD];
__device__ float g_v[ROWS * HD];
__device__ float g_wp[3 * 128 * 32 * 16];           // prepacked W fragments (tf32)
__device__ float g_po[(size_t)NPARTS * TQ * HD];    // partial O [part][q][d]
__device__ float g_pm[NPARTS * TQ];
__device__ float g_pl[NPARTS * TQ];

__device__ __forceinline__ float to_tf32(float f) {
    unsigned int u;
    asm("cvt.rna.tf32.f32 %0, %1;" : "=r"(u) : "f"(f));
    return __uint_as_float(u);
}

#define MMA_TF32(C, A0, A1, A2, A3, B0, B1)                                   \
    asm volatile(                                                             \
        "mma.sync.aligned.m16n8k8.row.col.f32.tf32.tf32.f32 "                 \
        "{%0,%1,%2,%3}, {%4,%5,%6,%7}, {%8,%9}, {%0,%1,%2,%3};"               \
        : "+f"((C)[0]), "+f"((C)[1]), "+f"((C)[2]), "+f"((C)[3])              \
        : "r"(A0), "r"(A1), "r"(A2), "r"(A3), "r"(B0), "r"(B1))

#define CP_ASYNC16(dst_u32, src_ptr)                                          \
    asm volatile("cp.async.cg.shared.global [%0], [%1], 16;"                  \
                 :: "r"(dst_u32), "l"(src_ptr))
#define CP_COMMIT() asm volatile("cp.async.commit_group;")
#define CP_WAIT1()  asm volatile("cp.async.wait_group 1;")
#define CP_WAIT0()  asm volatile("cp.async.wait_group 0;")

// ============================================================================
// Kernel 0: prepack W fragments, coalesced via smem bounce.
// grid = 24 (3 mi x 8 kk-blocks), 256 threads.
// Block (mi, kb): stage W rows [kb*128, kb*128+128) x 64 (tf32-converted,
// coalesced reads), then write fragment layout (fully coalesced writes).
// ============================================================================
__global__ __launch_bounds__(256) void prepack(const float* __restrict__ Wq,
                                               const float* __restrict__ Wk,
                                               const float* __restrict__ Wv) {
    __shared__ float Ws[128 * 64];   // 32KB
    const int mi = blockIdx.x >> 3;
    const int kb = blockIdx.x & 7;
    const int tid = threadIdx.x;
    const float* W = (mi == 0) ? Wq : (mi == 1 ? Wk : Wv);
    const float* Wblk = W + (size_t)(kb * 128) * HD;

    // coalesced load + convert: 2048 float4
#pragma unroll
    for (int i = 0; i < 8; ++i) {
        const int f = i * 256 + tid;
        float4 v = *(const float4*)(Wblk + f * 4);
        *(float4*)&Ws[f * 4] =
            make_float4(to_tf32(v.x), to_tf32(v.y), to_tf32(v.z), to_tf32(v.w));
    }
    __syncthreads();

    // coalesced fragment writes: 2048 float4
    // f -> (kk_l = f>>7, lane = (f>>2)&31, e4 = f&3)
#pragma unroll
    for (int i = 0; i < 8; ++i) {
        const int f    = i * 256 + tid;
        const int e4   = f & 3;
        const int lane = (f >> 2) & 31;
        const int kk_l = f >> 7;
        const int g = lane >> 2, tig = lane & 3;
        float o[4];
#pragma unroll
        for (int j = 0; j < 4; ++j) {
            const int e = e4 * 4 + j;
            const int nt = e >> 1, slot = e & 1;
            o[j] = Ws[(kk_l * 8 + tig + slot * 4) * HD + nt * 8 + g];
        }
        *(float4*)(g_wp + ((((size_t)mi * 128) + kb * 16 + kk_l) * 32 + lane) * 16 + e4 * 4) =
            make_float4(o[0], o[1], o[2], o[3]);
    }
}

// Dummy kernel: shifts ncu's captured launch (-s 5) onto qkv_tf32.
__global__ void ncu_shift() {}

// ============================================================================
// Kernel 1: fused QKV projection via tf32 mma, 12 warps/block.
// Warp w: mi = w>>2 (q/k/v), rows (w&3)*16..+16. Xs shared across all warps.
// BM=64, BK=32, 384 threads, grid = 128.
// ============================================================================
__global__ __launch_bounds__(384) void qkv_tf32(const float* __restrict__ x) {
    __shared__ float Xs[64][36];

    const int tid  = threadIdx.x;
    const int lane = tid & 31;
    const int wid  = tid >> 5;
    const int mi   = wid >> 2;
    const int mrow = (wid & 3) * 16;
    const int g    = lane >> 2;
    const int tig  = lane & 3;
    const int m0   = blockIdx.x * 64;

    // loader: 512 float4 over 384 threads (threads 0..127 carry 2)
    const int r0 = tid >> 3,         c0 = (tid & 7) * 4;
    const bool has2 = (tid < 128);
    const int e1 = tid + 384;
    const int r1 = e1 >> 3,          c1 = (e1 & 7) * 4;

    float c[8][4];
#pragma unroll
    for (int nt = 0; nt < 8; ++nt)
#pragma unroll
        for (int i = 0; i < 4; ++i) c[nt][i] = 0.f;

    float4 p0, p1;
    p0 = *(const float4*)(x + (size_t)(m0 + r0) * EMB + c0);
    if (has2) p1 = *(const float4*)(x + (size_t)(m0 + r1) * EMB + c1);
    *(float4*)&Xs[r0][c0] = make_float4(to_tf32(p0.x), to_tf32(p0.y), to_tf32(p0.z), to_tf32(p0.w));
    if (has2)
        *(float4*)&Xs[r1][c1] = make_float4(to_tf32(p1.x), to_tf32(p1.y), to_tf32(p1.z), to_tf32(p1.w));
    __syncthreads();

    const float* wpbase = g_wp + ((size_t)mi * 128 * 32 + lane) * 16;

    for (int k0 = 0; k0 < EMB; k0 += 32) {
        const bool hn = (k0 + 32 < EMB);
        if (hn) {
            p0 = *(const float4*)(x + (size_t)(m0 + r0) * EMB + k0 + 32 + c0);
            if (has2) p1 = *(const float4*)(x + (size_t)(m0 + r1) * EMB + k0 + 32 + c1);
        }

#pragma unroll
        for (int ks = 0; ks < 4; ++ks) {
            const int kk = (k0 >> 3) + ks;
            const float4* wp4 = (const float4*)(wpbase + (size_t)kk * 32 * 16);
            float bf[16];
            *(float4*)&bf[0]  = wp4[0];
            *(float4*)&bf[4]  = wp4[1];
            *(float4*)&bf[8]  = wp4[2];
            *(float4*)&bf[12] = wp4[3];

            const int kb = ks * 8;
            unsigned int a0 = __float_as_uint(Xs[mrow + g    ][kb + tig    ]);
            unsigned int a1 = __float_as_uint(Xs[mrow + g + 8][kb + tig    ]);
            unsigned int a2 = __float_as_uint(Xs[mrow + g    ][kb + tig + 4]);
            unsigned int a3 = __float_as_uint(Xs[mrow + g + 8][kb + tig + 4]);
#pragma unroll
            for (int nt = 0; nt < 8; ++nt) {
                unsigned int b0 = __float_as_uint(bf[nt * 2]);
                unsigned int b1 = __float_as_uint(bf[nt * 2 + 1]);
                MMA_TF32(c[nt], a0, a1, a2, a3, b0, b1);
            }
        }
        __syncthreads();
        if (hn) {
            *(float4*)&Xs[r0][c0] =
                make_float4(to_tf32(p0.x), to_tf32(p0.y), to_tf32(p0.z), to_tf32(p0.w));
            if (has2)
                *(float4*)&Xs[r1][c1] =
                    make_float4(to_tf32(p1.x), to_tf32(p1.y), to_tf32(p1.z), to_tf32(p1.w));
            __syncthreads();
        }
    }

    float* out = (mi == 0) ? g_q : (mi == 1 ? g_k : g_v);
    const int row0 = m0 + mrow + g;
#pragma unroll
    for (int nt = 0; nt < 8; ++nt) {
        const int col = nt * 8 + 2 * tig;
        *(float2*)&out[(size_t)row0       * HD + col] =
            make_float2(to_tf32(c[nt][0]), to_tf32(c[nt][1]));
        *(float2*)&out[(size_t)(row0 + 8) * HD + col] =
            make_float2(to_tf32(c[nt][2]), to_tf32(c[nt][3]));
    }
}

// ============================================================================
// Kernel 2: flash attention partial, 3-slot cp.async ring (unchanged R13).
// grid = (MAXCH, NQT, BATCH), 128 threads, 3 blocks/SM.
// ============================================================================
__global__ __launch_bounds__(128, 3) void attn_mma() {
    const int ch = blockIdx.x, qt = blockIdx.y, b = blockIdx.z;
    const int kstart = ch * KCH;
    const int kend   = min(kstart + KCH, (qt + 1) * TQ);
    if (kstart >= kend) return;

    extern __shared__ float sm[];
    float* Kb = sm;                               // [3][KT][KSTR]
    float* Vb = sm + KBUF_FLOATS;                 // [3][KT][VSTR]
    float* Pb = sm + KBUF_FLOATS + VBUF_FLOATS;   // [64][PSTR]
    const unsigned smem_k = (unsigned)__cvta_generic_to_shared(Kb);
    const unsigned smem_v = (unsigned)__cvta_generic_to_shared(Vb);

    const int tid  = threadIdx.x;
    const int lane = tid & 31;
    const int warp = tid >> 5;
    const int g    = lane >> 2;
    const int tig  = lane & 3;
    const int w16  = warp * 16;
    const int qw0  = qt * TQ + w16;

    int srow[4], scol[4];
#pragma unroll
    for (int i = 0; i < 4; ++i) {
        int e = i * 128 + tid;
        srow[i] = e >> 4; scol[i] = (e & 15) * 4;
    }
    const int nkt = (kend - kstart) / KT;

#pragma unroll
    for (int i = 0; i < 4; ++i) {
        const size_t gb = (size_t)(b * SEQ + kstart + srow[i]) * HD + scol[i];
        CP_ASYNC16(smem_k + (srow[i] * KSTR + scol[i]) * 4, g_k + gb);
        CP_ASYNC16(smem_v + (srow[i] * VSTR + scol[i]) * 4, g_v + gb);
    }
    CP_COMMIT();
    if (nkt > 1) {
#pragma unroll
        for (int i = 0; i < 4; ++i) {
            const size_t gb = (size_t)(b * SEQ + kstart + KT + srow[i]) * HD + scol[i];
            CP_ASYNC16(smem_k + ((KSLOT + srow[i] * KSTR + scol[i])) * 4, g_k + gb);
            CP_ASYNC16(smem_v + ((VSLOT + srow[i] * VSTR + scol[i])) * 4, g_v + gb);
        }
        CP_COMMIT();
    }

    float a[8][4];
    {
        const float* qb = g_q + (size_t)(b * SEQ + qw0) * HD;
        const float qs = SCALE * LOG2E;
#pragma unroll
        for (int ks = 0; ks < 8; ++ks) {
            a[ks][0] = qb[(size_t)g       * HD + ks * 8 + tig    ] * qs;
            a[ks][1] = qb[(size_t)(g + 8) * HD + ks * 8 + tig    ] * qs;
            a[ks][2] = qb[(size_t)g       * HD + ks * 8 + tig + 4] * qs;
            a[ks][3] = qb[(size_t)(g + 8) * HD + ks * 8 + tig + 4] * qs;
        }
    }

    float oc[8][4];
#pragma unroll
    for (int nt = 0; nt < 8; ++nt)
#pragma unroll
        for (int i = 0; i < 4; ++i) oc[nt][i] = 0.f;
    float m0r = -1e30f, m1r = -1e30f, l0 = 0.f, l1 = 0.f;

    int slot = 0;
    for (int t = 0; t < nkt; ++t) {
        const int kt0 = kstart + t * KT;
        float* Kc = Kb + slot * KSLOT;
        float* Vc = Vb + slot * VSLOT;

        if (t + 1 < nkt) { CP_WAIT1(); } else { CP_WAIT0(); }
        __syncthreads();

        if (t + 2 < nkt) {
            const int ps = (slot + 2) % 3;
#pragma unroll
            for (int i = 0; i < 4; ++i) {
                const size_t gb = (size_t)(b * SEQ + kt0 + 2 * KT + srow[i]) * HD + scol[i];
                CP_ASYNC16(smem_k + (ps * KSLOT + srow[i] * KSTR + scol[i]) * 4, g_k + gb);
                CP_ASYNC16(smem_v + (ps * VSLOT + srow[i] * VSTR + scol[i]) * 4, g_v + gb);
            }
            CP_COMMIT();
        }

        float s[4][4];
#pragma unroll
        for (int nt = 0; nt < 4; ++nt)
#pragma unroll
            for (int i = 0; i < 4; ++i) s[nt][i] = 0.f;
#pragma unroll
        for (int ks = 0; ks < 8; ++ks) {
            unsigned int a0 = __float_as_uint(a[ks][0]);
            unsigned int a1 = __float_as_uint(a[ks][1]);
            unsigned int a2 = __float_as_uint(a[ks][2]);
            unsigned int a3 = __float_as_uint(a[ks][3]);
#pragma unroll
            for (int nt = 0; nt < 4; ++nt) {
                unsigned int b0 = __float_as_uint(Kc[(nt * 8 + g) * KSTR + ks * 8 + tig    ]);
                unsigned int b1 = __float_as_uint(Kc[(nt * 8 + g) * KSTR + ks * 8 + tig + 4]);
                MMA_TF32(s[nt], a0, a1, a2, a3, b0, b1);
            }
        }

        if (kt0 + KT - 1 > qw0) {
#pragma unroll
            for (int nt = 0; nt < 4; ++nt) {
                const int col = kt0 + nt * 8 + 2 * tig;
                if (col     > qw0 + g)     s[nt][0] = -1e30f;
                if (col + 1 > qw0 + g)     s[nt][1] = -1e30f;
                if (col     > qw0 + g + 8) s[nt][2] = -1e30f;
                if (col + 1 > qw0 + g + 8) s[nt][3] = -1e30f;
            }
        }

        float mx0 = -1e30f, mx1 = -1e30f;
#pragma unroll
        for (int nt = 0; nt < 4; ++nt) {
            mx0 = fmaxf(mx0, fmaxf(s[nt][0], s[nt][1]));
            mx1 = fmaxf(mx1, fmaxf(s[nt][2], s[nt][3]));
        }
        mx0 = fmaxf(mx0, __shfl_xor_sync(0xffffffffu, mx0, 1));
        mx0 = fmaxf(mx0, __shfl_xor_sync(0xffffffffu, mx0, 2));
        mx1 = fmaxf(mx1, __shfl_xor_sync(0xffffffffu, mx1, 1));
        mx1 = fmaxf(mx1, __shfl_xor_sync(0xffffffffu, mx1, 2));

        const float mn0 = fmaxf(m0r, mx0), mn1 = fmaxf(m1r, mx1);
        const float corr0 = exp2f(m0r - mn0), corr1 = exp2f(m1r - mn1);

        float sum0 = 0.f, sum1 = 0.f;
#pragma unroll
        for (int nt = 0; nt < 4; ++nt) {
            float p0 = to_tf32(exp2f(s[nt][0] - mn0));
            float p1 = to_tf32(exp2f(s[nt][1] - mn0));
            float p2 = to_tf32(exp2f(s[nt][2] - mn1));
            float p3 = to_tf32(exp2f(s[nt][3] - mn1));
            sum0 += p0 + p1;
            sum1 += p2 + p3;
            *(float2*)&Pb[(w16 + g    ) * PSTR + nt * 8 + 2 * tig] = make_float2(p0, p1);
            *(float2*)&Pb[(w16 + g + 8) * PSTR + nt * 8 + 2 * tig] = make_float2(p2, p3);
        }
        sum0 += __shfl_xor_sync(0xffffffffu, sum0, 1);
        sum0 += __shfl_xor_sync(0xffffffffu, sum0, 2);
        sum1 += __shfl_xor_sync(0xffffffffu, sum1, 1);
        sum1 += __shfl_xor_sync(0xffffffffu, sum1, 2);

        l0 = l0 * corr0 + sum0;
        l1 = l1 * corr1 + sum1;
        m0r = mn0; m1r = mn1;
#pragma unroll
        for (int nt = 0; nt < 8; ++nt) {
            oc[nt][0] *= corr0; oc[nt][1] *= corr0;
            oc[nt][2] *= corr1; oc[nt][3] *= corr1;
        }
        __syncwarp();

#pragma unroll
        for (int ks = 0; ks < 4; ++ks) {
            unsigned int p0 = __float_as_uint(Pb[(w16 + g    ) * PSTR + ks * 8 + tig    ]);
            unsigned int p1 = __float_as_uint(Pb[(w16 + g + 8) * PSTR + ks * 8 + tig    ]);
            unsigned int p2 = __float_as_uint(Pb[(w16 + g    ) * PSTR + ks * 8 + tig + 4]);
            unsigned int p3 = __float_as_uint(Pb[(w16 + g + 8) * PSTR + ks * 8 + tig + 4]);
#pragma unroll
            for (int nt = 0; nt < 8; ++nt) {
                unsigned int b0 = __float_as_uint(Vc[(ks * 8 + tig    ) * VSTR + nt * 8 + g]);
                unsigned int b1 = __float_as_uint(Vc[(ks * 8 + tig + 4) * VSTR + nt * 8 + g]);
                MMA_TF32(oc[nt], p0, p1, p2, p3, b0, b1);
            }
        }
        slot = (slot + 1) % 3;
    }

    const int part = (b * NQT + qt) * MAXCH + ch;
    float* po = g_po + (size_t)part * TQ * HD;
#pragma unroll
    for (int nt = 0; nt < 8; ++nt) {
        const int col = nt * 8 + 2 * tig;
        *(float2*)&po[(size_t)(w16 + g)     * HD + col] = make_float2(oc[nt][0], oc[nt][1]);
        *(float2*)&po[(size_t)(w16 + g + 8) * HD + col] = make_float2(oc[nt][2], oc[nt][3]);
    }
    g_pm[part * TQ + w16 + g]     = m0r;
    g_pm[part * TQ + w16 + g + 8] = m1r;
    g_pl[part * TQ + w16 + g]     = l0;
    g_pl[part * TQ + w16 + g + 8] = l1;
}

// ============================================================================
// Kernel 3: combine — one thread per float4 of output.
// ============================================================================
__global__ __launch_bounds__(256) void attn_combine(float* __restrict__ out) {
    const int idx = blockIdx.x * 256 + threadIdx.x;
    const int d4  = (idx & 15) * 4;
    const int row = idx >> 4;
    const int b   = row >> 11;
    const int qr  = row & (SEQ - 1);
    const int qt  = qr >> 6;
    const int rin = qr & (TQ - 1);
    const int nch = (qt + 4) >> 2;
    const int pbase = (b * NQT + qt) * MAXCH;

    float M = -1e30f;
#pragma unroll 4
    for (int c = 0; c < nch; ++c)
        M = fmaxf(M, g_pm[(pbase + c) * TQ + rin]);

    float L = 0.f;
    float4 o = make_float4(0.f, 0.f, 0.f, 0.f);
#pragma unroll 4
    for (int c = 0; c < nch; ++c) {
        const int part = pbase + c;
        const float w = exp2f(g_pm[part * TQ + rin] - M);
        L += g_pl[part * TQ + rin] * w;
        float4 v = *(const float4*)(g_po + ((size_t)part * TQ + rin) * HD + d4);
        o.x += w * v.x; o.y += w * v.y; o.z += w * v.z; o.w += w * v.w;
    }
    const float inv = 1.f / L;
    *(float4*)(out + (size_t)row * HD + d4) =
        make_float4(o.x * inv, o.y * inv, o.z * inv, o.w * inv);
}

// ============================================================================
// Launch
// ============================================================================
extern "C" void kernel_launch(void* const* d_in, const int* in_sizes, int n_in,
                              void* d_out, int out_size) {
    (void)in_sizes; (void)n_in; (void)out_size;
    const float* x  = (const float*)d_in[0];
    const float* Wq = (const float*)d_in[1];
    const float* Wk = (const float*)d_in[2];
    const float* Wv = (const float*)d_in[3];
    float* out = (float*)d_out;

    static int smem_set = 0;
    if (!smem_set) {
        cudaFuncSetAttribute(attn_mma, cudaFuncAttributeMaxDynamicSharedMemorySize,
                             ATTN_SMEM_BYTES);
        smem_set = 1;
    }

    prepack     <<<24, 256>>>(Wq, Wk, Wv);
    ncu_shift   <<<1, 32>>>();   // align ncu -s 5 capture onto qkv_tf32
    ncu_shift   <<<1, 32>>>();
    qkv_tf32    <<<ROWS / 64, 384>>>(x);
    attn_mma    <<<dim3(MAXCH, NQT, BATCH), 128, ATTN_SMEM_BYTES>>>();
    attn_combine<<<(ROWS * HD / 4) / 256, 256>>>(out);
}

// round 15
// speedup vs baseline: 1.3873x; 1.3054x over previous
#include <cuda_runtime.h>
#include <cuda_bf16.h>
#include <math.h>
#include <stdint.h>

#define EMB   1024
#define HD    64
#define BATCH 4
#define SEQ   2048
#define ROWS  (BATCH * SEQ)       // 8192
#define SCALE 0.03125f            // 1/sqrt(1024)
#define LOG2E 1.4426950408889634f

// attention tiling
#define TQ    64                  // queries per block (4 warps x 16 rows)
#define NQT   (SEQ / TQ)          // 32
#define KCH   256                 // keys per split chunk
#define MAXCH (SEQ / KCH)         // 8
#define KT    32                  // keys per inner tile
#define NPARTS (BATCH * NQT * MAXCH)   // 1024

// attn dynamic smem: K[3][32][68], V[3][32][72], P[64][36]
#define KSTR  68
#define VSTR  72
#define PSTR  36
#define KSLOT (KT * KSTR)
#define VSLOT (KT * VSTR)
#define KBUF_FLOATS (3 * KSLOT)
#define VBUF_FLOATS (3 * VSLOT)
#define PBUF_FLOATS (TQ * PSTR)
#define ATTN_SMEM_BYTES ((KBUF_FLOATS + VBUF_FLOATS + PBUF_FLOATS) * 4)

// ---------------- scratch (no allocations allowed) ----------------
__device__ float g_q[ROWS * HD];
__device__ float g_k[ROWS * HD];
__device__ float g_v[ROWS * HD];
// W fragments, layout [mi][kk][e4][lane][4]: LDG.128 is lane-contiguous.
__device__ float g_wp[3 * 128 * 4 * 32 * 4];
__device__ float g_po[(size_t)NPARTS * TQ * HD];    // partial O [part][q][d]
__device__ float g_pm[NPARTS * TQ];
__device__ float g_pl[NPARTS * TQ];

__device__ __forceinline__ float to_tf32(float f) {
    unsigned int u;
    asm("cvt.rna.tf32.f32 %0, %1;" : "=r"(u) : "f"(f));
    return __uint_as_float(u);
}

#define MMA_TF32(C, A0, A1, A2, A3, B0, B1)                                   \
    asm volatile(                                                             \
        "mma.sync.aligned.m16n8k8.row.col.f32.tf32.tf32.f32 "                 \
        "{%0,%1,%2,%3}, {%4,%5,%6,%7}, {%8,%9}, {%0,%1,%2,%3};"               \
        : "+f"((C)[0]), "+f"((C)[1]), "+f"((C)[2]), "+f"((C)[3])              \
        : "r"(A0), "r"(A1), "r"(A2), "r"(A3), "r"(B0), "r"(B1))

#define CP_ASYNC16(dst_u32, src_ptr)                                          \
    asm volatile("cp.async.cg.shared.global [%0], [%1], 16;"                  \
                 :: "r"(dst_u32), "l"(src_ptr))
#define CP_COMMIT() asm volatile("cp.async.commit_group;")
#define CP_WAIT1()  asm volatile("cp.async.wait_group 1;")
#define CP_WAIT0()  asm volatile("cp.async.wait_group 0;")

// ============================================================================
// Kernel 0: prepack W fragments, coalesced via smem bounce.
// grid = 24 (3 mi x 8 kk-blocks), 256 threads.
// New layout: g_wp[(((mi*128+kk)*4 + e4)*32 + lane)*4 + j]
//   where fragment element e = e4*4+j, nt = e>>1, slot = e&1:
//   value = tf32(W[kk*8 + tig + slot*4][nt*8 + g]),  lane = g*4+tig.
// ============================================================================
__global__ __launch_bounds__(256) void prepack(const float* __restrict__ Wq,
                                               const float* __restrict__ Wk,
                                               const float* __restrict__ Wv) {
    __shared__ float Ws[128 * 64];   // 32KB
    const int mi = blockIdx.x >> 3;
    const int kb = blockIdx.x & 7;
    const int tid = threadIdx.x;
    const float* W = (mi == 0) ? Wq : (mi == 1 ? Wk : Wv);
    const float* Wblk = W + (size_t)(kb * 128) * HD;

    // coalesced load + convert: 2048 float4
#pragma unroll
    for (int i = 0; i < 8; ++i) {
        const int f = i * 256 + tid;
        float4 v = *(const float4*)(Wblk + f * 4);
        *(float4*)&Ws[f * 4] =
            make_float4(to_tf32(v.x), to_tf32(v.y), to_tf32(v.z), to_tf32(v.w));
    }
    __syncthreads();

    // coalesced fragment writes: f -> (lane = f&31, e4 = (f>>5)&3, kk_l = f>>7)
#pragma unroll
    for (int i = 0; i < 8; ++i) {
        const int f    = i * 256 + tid;
        const int lane = f & 31;
        const int e4   = (f >> 5) & 3;
        const int kk_l = f >> 7;
        const int g = lane >> 2, tig = lane & 3;
        float o[4];
#pragma unroll
        for (int j = 0; j < 4; ++j) {
            const int e = e4 * 4 + j;
            const int nt = e >> 1, slot = e & 1;
            o[j] = Ws[(kk_l * 8 + tig + slot * 4) * HD + nt * 8 + g];
        }
        const size_t kk = (size_t)mi * 128 + kb * 16 + kk_l;
        *(float4*)(g_wp + ((kk * 4 + e4) * 32 + lane) * 4) =
            make_float4(o[0], o[1], o[2], o[3]);
    }
}

// Dummy kernel: shifts ncu's captured launch (-s 5) onto qkv_tf32.
__global__ void ncu_shift() {}

// ============================================================================
// Kernel 1: fused QKV projection via tf32 mma, 12 warps/block.
// Warp w: mi = w>>2 (q/k/v), rows (w&3)*16..+16. Xs double-buffered:
// one __syncthreads per k0 tile; x LDG overlapped with MMA.
// BM=64, BK=32, 384 threads, grid = 128.
// ============================================================================
__global__ __launch_bounds__(384) void qkv_tf32(const float* __restrict__ x) {
    __shared__ float Xs[2][64][36];

    const int tid  = threadIdx.x;
    const int lane = tid & 31;
    const int wid  = tid >> 5;
    const int mi   = wid >> 2;
    const int mrow = (wid & 3) * 16;
    const int g    = lane >> 2;
    const int tig  = lane & 3;
    const int m0   = blockIdx.x * 64;

    // loader: 512 float4 over 384 threads (threads 0..127 carry 2)
    const int r0 = tid >> 3,         c0 = (tid & 7) * 4;
    const bool has2 = (tid < 128);
    const int e1 = tid + 384;
    const int r1 = e1 >> 3,          c1 = (e1 & 7) * 4;

    float c[8][4];
#pragma unroll
    for (int nt = 0; nt < 8; ++nt)
#pragma unroll
        for (int i = 0; i < 4; ++i) c[nt][i] = 0.f;

    // preload tile 0 into buffer 0
    {
        float4 p0 = *(const float4*)(x + (size_t)(m0 + r0) * EMB + c0);
        *(float4*)&Xs[0][r0][c0] =
            make_float4(to_tf32(p0.x), to_tf32(p0.y), to_tf32(p0.z), to_tf32(p0.w));
        if (has2) {
            float4 p1 = *(const float4*)(x + (size_t)(m0 + r1) * EMB + c1);
            *(float4*)&Xs[0][r1][c1] =
                make_float4(to_tf32(p1.x), to_tf32(p1.y), to_tf32(p1.z), to_tf32(p1.w));
        }
    }
    __syncthreads();

    const float4* wpbase = (const float4*)g_wp + (size_t)mi * 128 * 4 * 32 + lane;

    for (int t = 0; t < EMB / 32; ++t) {
        const int cur = t & 1;
        const bool hn = (t + 1 < EMB / 32);

        float4 p0, p1;
        if (hn) {   // issue next x tile loads; consumed after compute
            const int kn = (t + 1) * 32;
            p0 = *(const float4*)(x + (size_t)(m0 + r0) * EMB + kn + c0);
            if (has2) p1 = *(const float4*)(x + (size_t)(m0 + r1) * EMB + kn + c1);
        }

#pragma unroll
        for (int ks = 0; ks < 4; ++ks) {
            const int kk = t * 4 + ks;
            const float4* wp4 = wpbase + (size_t)kk * 4 * 32;
            float bf[16];
            *(float4*)&bf[0]  = wp4[0];        // lane-contiguous 512B
            *(float4*)&bf[4]  = wp4[32];
            *(float4*)&bf[8]  = wp4[64];
            *(float4*)&bf[12] = wp4[96];

            const int kb = ks * 8;
            unsigned int a0 = __float_as_uint(Xs[cur][mrow + g    ][kb + tig    ]);
            unsigned int a1 = __float_as_uint(Xs[cur][mrow + g + 8][kb + tig    ]);
            unsigned int a2 = __float_as_uint(Xs[cur][mrow + g    ][kb + tig + 4]);
            unsigned int a3 = __float_as_uint(Xs[cur][mrow + g + 8][kb + tig + 4]);
#pragma unroll
            for (int nt = 0; nt < 8; ++nt) {
                unsigned int b0 = __float_as_uint(bf[nt * 2]);
                unsigned int b1 = __float_as_uint(bf[nt * 2 + 1]);
                MMA_TF32(c[nt], a0, a1, a2, a3, b0, b1);
            }
        }

        if (hn) {   // store next tile to other buffer (its readers done at t-1 barrier)
            const int nxt = cur ^ 1;
            *(float4*)&Xs[nxt][r0][c0] =
                make_float4(to_tf32(p0.x), to_tf32(p0.y), to_tf32(p0.z), to_tf32(p0.w));
            if (has2)
                *(float4*)&Xs[nxt][r1][c1] =
                    make_float4(to_tf32(p1.x), to_tf32(p1.y), to_tf32(p1.z), to_tf32(p1.w));
        }
        __syncthreads();   // one barrier per k0 tile
    }

    float* out = (mi == 0) ? g_q : (mi == 1 ? g_k : g_v);
    const int row0 = m0 + mrow + g;
#pragma unroll
    for (int nt = 0; nt < 8; ++nt) {
        const int col = nt * 8 + 2 * tig;
        *(float2*)&out[(size_t)row0       * HD + col] =
            make_float2(to_tf32(c[nt][0]), to_tf32(c[nt][1]));
        *(float2*)&out[(size_t)(row0 + 8) * HD + col] =
            make_float2(to_tf32(c[nt][2]), to_tf32(c[nt][3]));
    }
}

// ============================================================================
// Kernel 2: flash attention partial, 3-slot cp.async ring (unchanged R13).
// grid = (MAXCH, NQT, BATCH), 128 threads, 3 blocks/SM.
// ============================================================================
__global__ __launch_bounds__(128, 3) void attn_mma() {
    const int ch = blockIdx.x, qt = blockIdx.y, b = blockIdx.z;
    const int kstart = ch * KCH;
    const int kend   = min(kstart + KCH, (qt + 1) * TQ);
    if (kstart >= kend) return;

    extern __shared__ float sm[];
    float* Kb = sm;
    float* Vb = sm + KBUF_FLOATS;
    float* Pb = sm + KBUF_FLOATS + VBUF_FLOATS;
    const unsigned smem_k = (unsigned)__cvta_generic_to_shared(Kb);
    const unsigned smem_v = (unsigned)__cvta_generic_to_shared(Vb);

    const int tid  = threadIdx.x;
    const int lane = tid & 31;
    const int warp = tid >> 5;
    const int g    = lane >> 2;
    const int tig  = lane & 3;
    const int w16  = warp * 16;
    const int qw0  = qt * TQ + w16;

    int srow[4], scol[4];
#pragma unroll
    for (int i = 0; i < 4; ++i) {
        int e = i * 128 + tid;
        srow[i] = e >> 4; scol[i] = (e & 15) * 4;
    }
    const int nkt = (kend - kstart) / KT;

#pragma unroll
    for (int i = 0; i < 4; ++i) {
        const size_t gb = (size_t)(b * SEQ + kstart + srow[i]) * HD + scol[i];
        CP_ASYNC16(smem_k + (srow[i] * KSTR + scol[i]) * 4, g_k + gb);
        CP_ASYNC16(smem_v + (srow[i] * VSTR + scol[i]) * 4, g_v + gb);
    }
    CP_COMMIT();
    if (nkt > 1) {
#pragma unroll
        for (int i = 0; i < 4; ++i) {
            const size_t gb = (size_t)(b * SEQ + kstart + KT + srow[i]) * HD + scol[i];
            CP_ASYNC16(smem_k + ((KSLOT + srow[i] * KSTR + scol[i])) * 4, g_k + gb);
            CP_ASYNC16(smem_v + ((VSLOT + srow[i] * VSTR + scol[i])) * 4, g_v + gb);
        }
        CP_COMMIT();
    }

    float a[8][4];
    {
        const float* qb = g_q + (size_t)(b * SEQ + qw0) * HD;
        const float qs = SCALE * LOG2E;
#pragma unroll
        for (int ks = 0; ks < 8; ++ks) {
            a[ks][0] = qb[(size_t)g       * HD + ks * 8 + tig    ] * qs;
            a[ks][1] = qb[(size_t)(g + 8) * HD + ks * 8 + tig    ] * qs;
            a[ks][2] = qb[(size_t)g       * HD + ks * 8 + tig + 4] * qs;
            a[ks][3] = qb[(size_t)(g + 8) * HD + ks * 8 + tig + 4] * qs;
        }
    }

    float oc[8][4];
#pragma unroll
    for (int nt = 0; nt < 8; ++nt)
#pragma unroll
        for (int i = 0; i < 4; ++i) oc[nt][i] = 0.f;
    float m0r = -1e30f, m1r = -1e30f, l0 = 0.f, l1 = 0.f;

    int slot = 0;
    for (int t = 0; t < nkt; ++t) {
        const int kt0 = kstart + t * KT;
        float* Kc = Kb + slot * KSLOT;
        float* Vc = Vb + slot * VSLOT;

        if (t + 1 < nkt) { CP_WAIT1(); } else { CP_WAIT0(); }
        __syncthreads();

        if (t + 2 < nkt) {
            const int ps = (slot + 2) % 3;
#pragma unroll
            for (int i = 0; i < 4; ++i) {
                const size_t gb = (size_t)(b * SEQ + kt0 + 2 * KT + srow[i]) * HD + scol[i];
                CP_ASYNC16(smem_k + (ps * KSLOT + srow[i] * KSTR + scol[i]) * 4, g_k + gb);
                CP_ASYNC16(smem_v + (ps * VSLOT + srow[i] * VSTR + scol[i]) * 4, g_v + gb);
            }
            CP_COMMIT();
        }

        float s[4][4];
#pragma unroll
        for (int nt = 0; nt < 4; ++nt)
#pragma unroll
            for (int i = 0; i < 4; ++i) s[nt][i] = 0.f;
#pragma unroll
        for (int ks = 0; ks < 8; ++ks) {
            unsigned int a0 = __float_as_uint(a[ks][0]);
            unsigned int a1 = __float_as_uint(a[ks][1]);
            unsigned int a2 = __float_as_uint(a[ks][2]);
            unsigned int a3 = __float_as_uint(a[ks][3]);
#pragma unroll
            for (int nt = 0; nt < 4; ++nt) {
                unsigned int b0 = __float_as_uint(Kc[(nt * 8 + g) * KSTR + ks * 8 + tig    ]);
                unsigned int b1 = __float_as_uint(Kc[(nt * 8 + g) * KSTR + ks * 8 + tig + 4]);
                MMA_TF32(s[nt], a0, a1, a2, a3, b0, b1);
            }
        }

        if (kt0 + KT - 1 > qw0) {
#pragma unroll
            for (int nt = 0; nt < 4; ++nt) {
                const int col = kt0 + nt * 8 + 2 * tig;
                if (col     > qw0 + g)     s[nt][0] = -1e30f;
                if (col + 1 > qw0 + g)     s[nt][1] = -1e30f;
                if (col     > qw0 + g + 8) s[nt][2] = -1e30f;
                if (col + 1 > qw0 + g + 8) s[nt][3] = -1e30f;
            }
        }

        float mx0 = -1e30f, mx1 = -1e30f;
#pragma unroll
        for (int nt = 0; nt < 4; ++nt) {
            mx0 = fmaxf(mx0, fmaxf(s[nt][0], s[nt][1]));
            mx1 = fmaxf(mx1, fmaxf(s[nt][2], s[nt][3]));
        }
        mx0 = fmaxf(mx0, __shfl_xor_sync(0xffffffffu, mx0, 1));
        mx0 = fmaxf(mx0, __shfl_xor_sync(0xffffffffu, mx0, 2));
        mx1 = fmaxf(mx1, __shfl_xor_sync(0xffffffffu, mx1, 1));
        mx1 = fmaxf(mx1, __shfl_xor_sync(0xffffffffu, mx1, 2));

        const float mn0 = fmaxf(m0r, mx0), mn1 = fmaxf(m1r, mx1);
        const float corr0 = exp2f(m0r - mn0), corr1 = exp2f(m1r - mn1);

        float sum0 = 0.f, sum1 = 0.f;
#pragma unroll
        for (int nt = 0; nt < 4; ++nt) {
            float p0 = to_tf32(exp2f(s[nt][0] - mn0));
            float p1 = to_tf32(exp2f(s[nt][1] - mn0));
            float p2 = to_tf32(exp2f(s[nt][2] - mn1));
            float p3 = to_tf32(exp2f(s[nt][3] - mn1));
            sum0 += p0 + p1;
            sum1 += p2 + p3;
            *(float2*)&Pb[(w16 + g    ) * PSTR + nt * 8 + 2 * tig] = make_float2(p0, p1);
            *(float2*)&Pb[(w16 + g + 8) * PSTR + nt * 8 + 2 * tig] = make_float2(p2, p3);
        }
        sum0 += __shfl_xor_sync(0xffffffffu, sum0, 1);
        sum0 += __shfl_xor_sync(0xffffffffu, sum0, 2);
        sum1 += __shfl_xor_sync(0xffffffffu, sum1, 1);
        sum1 += __shfl_xor_sync(0xffffffffu, sum1, 2);

        l0 = l0 * corr0 + sum0;
        l1 = l1 * corr1 + sum1;
        m0r = mn0; m1r = mn1;
#pragma unroll
        for (int nt = 0; nt < 8; ++nt) {
            oc[nt][0] *= corr0; oc[nt][1] *= corr0;
            oc[nt][2] *= corr1; oc[nt][3] *= corr1;
        }
        __syncwarp();

#pragma unroll
        for (int ks = 0; ks < 4; ++ks) {
            unsigned int p0 = __float_as_uint(Pb[(w16 + g    ) * PSTR + ks * 8 + tig    ]);
            unsigned int p1 = __float_as_uint(Pb[(w16 + g + 8) * PSTR + ks * 8 + tig    ]);
            unsigned int p2 = __float_as_uint(Pb[(w16 + g    ) * PSTR + ks * 8 + tig + 4]);
            unsigned int p3 = __float_as_uint(Pb[(w16 + g + 8) * PSTR + ks * 8 + tig + 4]);
#pragma unroll
            for (int nt = 0; nt < 8; ++nt) {
                unsigned int b0 = __float_as_uint(Vc[(ks * 8 + tig    ) * VSTR + nt * 8 + g]);
                unsigned int b1 = __float_as_uint(Vc[(ks * 8 + tig + 4) * VSTR + nt * 8 + g]);
                MMA_TF32(oc[nt], p0, p1, p2, p3, b0, b1);
            }
        }
        slot = (slot + 1) % 3;
    }

    const int part = (b * NQT + qt) * MAXCH + ch;
    float* po = g_po + (size_t)part * TQ * HD;
#pragma unroll
    for (int nt = 0; nt < 8; ++nt) {
        const int col = nt * 8 + 2 * tig;
        *(float2*)&po[(size_t)(w16 + g)     * HD + col] = make_float2(oc[nt][0], oc[nt][1]);
        *(float2*)&po[(size_t)(w16 + g + 8) * HD + col] = make_float2(oc[nt][2], oc[nt][3]);
    }
    g_pm[part * TQ + w16 + g]     = m0r;
    g_pm[part * TQ + w16 + g + 8] = m1r;
    g_pl[part * TQ + w16 + g]     = l0;
    g_pl[part * TQ + w16 + g + 8] = l1;
}

// ============================================================================
// Kernel 3: combine — one thread per float4 of output.
// ============================================================================
__global__ __launch_bounds__(256) void attn_combine(float* __restrict__ out) {
    const int idx = blockIdx.x * 256 + threadIdx.x;
    const int d4  = (idx & 15) * 4;
    const int row = idx >> 4;
    const int b   = row >> 11;
    const int qr  = row & (SEQ - 1);
    const int qt  = qr >> 6;
    const int rin = qr & (TQ - 1);
    const int nch = (qt + 4) >> 2;
    const int pbase = (b * NQT + qt) * MAXCH;

    float M = -1e30f;
#pragma unroll 4
    for (int c = 0; c < nch; ++c)
        M = fmaxf(M, g_pm[(pbase + c) * TQ + rin]);

    float L = 0.f;
    float4 o = make_float4(0.f, 0.f, 0.f, 0.f);
#pragma unroll 4
    for (int c = 0; c < nch; ++c) {
        const int part = pbase + c;
        const float w = exp2f(g_pm[part * TQ + rin] - M);
        L += g_pl[part * TQ + rin] * w;
        float4 v = *(const float4*)(g_po + ((size_t)part * TQ + rin) * HD + d4);
        o.x += w * v.x; o.y += w * v.y; o.z += w * v.z; o.w += w * v.w;
    }
    const float inv = 1.f / L;
    *(float4*)(out + (size_t)row * HD + d4) =
        make_float4(o.x * inv, o.y * inv, o.z * inv, o.w * inv);
}

// ============================================================================
// Launch
// ============================================================================
extern "C" void kernel_launch(void* const* d_in, const int* in_sizes, int n_in,
                              void* d_out, int out_size) {
    (void)in_sizes; (void)n_in; (void)out_size;
    const float* x  = (const float*)d_in[0];
    const float* Wq = (const float*)d_in[1];
    const float* Wk = (const float*)d_in[2];
    const float* Wv = (const float*)d_in[3];
    float* out = (float*)d_out;

    static int smem_set = 0;
    if (!smem_set) {
        cudaFuncSetAttribute(attn_mma, cudaFuncAttributeMaxDynamicSharedMemorySize,
                             ATTN_SMEM_BYTES);
        smem_set = 1;
    }

    prepack     <<<24, 256>>>(Wq, Wk, Wv);
    ncu_shift   <<<1, 32>>>();   // align ncu -s 5 capture onto qkv_tf32
    ncu_shift   <<<1, 32>>>();
    qkv_tf32    <<<ROWS / 64, 384>>>(x);
    attn_mma    <<<dim3(MAXCH, NQT, BATCH), 128, ATTN_SMEM_BYTES>>>();
    attn_combine<<<(ROWS * HD / 4) / 256, 256>>>(out);
}

// round 16
// speedup vs baseline: 1.6916x; 1.2193x over previous
#include <cuda_runtime.h>
#include <cuda_bf16.h>
#include <math.h>
#include <stdint.h>

#define EMB   1024
#define HD    64
#define BATCH 4
#define SEQ   2048
#define ROWS  (BATCH * SEQ)       // 8192
#define SCALE 0.03125f            // 1/sqrt(1024)
#define LOG2E 1.4426950408889634f

// attention tiling
#define TQ    64                  // queries per block (4 warps x 16 rows)
#define NQT   (SEQ / TQ)          // 32
#define KCH   256                 // keys per split chunk
#define MAXCH (SEQ / KCH)         // 8
#define KT    32                  // keys per inner tile
#define NPARTS (BATCH * NQT * MAXCH)   // 1024

// attn dynamic smem: K[3][32][68], V[3][32][72], P[64][36]
#define KSTR  68
#define VSTR  72
#define PSTR  36
#define KSLOT (KT * KSTR)
#define VSLOT (KT * VSTR)
#define KBUF_FLOATS (3 * KSLOT)
#define VBUF_FLOATS (3 * VSLOT)
#define PBUF_FLOATS (TQ * PSTR)
#define ATTN_SMEM_BYTES ((KBUF_FLOATS + VBUF_FLOATS + PBUF_FLOATS) * 4)

// ---------------- scratch (no allocations allowed) ----------------
__device__ float g_q[ROWS * HD];
__device__ float g_k[ROWS * HD];
__device__ float g_v[ROWS * HD];
// W fragments, layout [mi][kk][e4][lane][4]: LDG.128 is lane-contiguous.
__device__ float g_wp[3 * 128 * 4 * 32 * 4];
__device__ float g_po[(size_t)NPARTS * TQ * HD];    // partial O [part][q][d]
__device__ float g_pm[NPARTS * TQ];
__device__ float g_pl[NPARTS * TQ];

__device__ __forceinline__ float to_tf32(float f) {
    unsigned int u;
    asm("cvt.rna.tf32.f32 %0, %1;" : "=r"(u) : "f"(f));
    return __uint_as_float(u);
}

#define MMA_TF32(C, A0, A1, A2, A3, B0, B1)                                   \
    asm volatile(                                                             \
        "mma.sync.aligned.m16n8k8.row.col.f32.tf32.tf32.f32 "                 \
        "{%0,%1,%2,%3}, {%4,%5,%6,%7}, {%8,%9}, {%0,%1,%2,%3};"               \
        : "+f"((C)[0]), "+f"((C)[1]), "+f"((C)[2]), "+f"((C)[3])              \
        : "r"(A0), "r"(A1), "r"(A2), "r"(A3), "r"(B0), "r"(B1))

#define CP_ASYNC16(dst_u32, src_ptr)                                          \
    asm volatile("cp.async.cg.shared.global [%0], [%1], 16;"                  \
                 :: "r"(dst_u32), "l"(src_ptr))
#define CP_COMMIT() asm volatile("cp.async.commit_group;")
#define CP_WAIT1()  asm volatile("cp.async.wait_group 1;")
#define CP_WAIT0()  asm volatile("cp.async.wait_group 0;")

// ============================================================================
// Kernel 0: prepack W fragments, coalesced via smem bounce (unchanged R15).
// g_wp[(((mi*128+kk)*4 + e4)*32 + lane)*4 + j],
//   e = e4*4+j, nt = e>>1, slot = e&1:
//   value = tf32(W[kk*8 + tig + slot*4][nt*8 + g]),  lane = g*4+tig.
// ============================================================================
__global__ __launch_bounds__(256) void prepack(const float* __restrict__ Wq,
                                               const float* __restrict__ Wk,
                                               const float* __restrict__ Wv) {
    __shared__ float Ws[128 * 64];   // 32KB
    const int mi = blockIdx.x >> 3;
    const int kb = blockIdx.x & 7;
    const int tid = threadIdx.x;
    const float* W = (mi == 0) ? Wq : (mi == 1 ? Wk : Wv);
    const float* Wblk = W + (size_t)(kb * 128) * HD;

#pragma unroll
    for (int i = 0; i < 8; ++i) {
        const int f = i * 256 + tid;
        float4 v = *(const float4*)(Wblk + f * 4);
        *(float4*)&Ws[f * 4] =
            make_float4(to_tf32(v.x), to_tf32(v.y), to_tf32(v.z), to_tf32(v.w));
    }
    __syncthreads();

#pragma unroll
    for (int i = 0; i < 8; ++i) {
        const int f    = i * 256 + tid;
        const int lane = f & 31;
        const int e4   = (f >> 5) & 3;
        const int kk_l = f >> 7;
        const int g = lane >> 2, tig = lane & 3;
        float o[4];
#pragma unroll
        for (int j = 0; j < 4; ++j) {
            const int e = e4 * 4 + j;
            const int nt = e >> 1, slot = e & 1;
            o[j] = Ws[(kk_l * 8 + tig + slot * 4) * HD + nt * 8 + g];
        }
        const size_t kk = (size_t)mi * 128 + kb * 16 + kk_l;
        *(float4*)(g_wp + ((kk * 4 + e4) * 32 + lane) * 4) =
            make_float4(o[0], o[1], o[2], o[3]);
    }
}

// Dummy kernel: shifts ncu's captured launch (-s 5) onto qkv_tf32.
__global__ void ncu_shift() {}

// ============================================================================
// Kernel 1: fused QKV projection, BM=32, 6 warps, depth-2 B prefetch.
// Warp w: mi = w>>1 (q/k/v), rows (w&1)*16..+16 of the 32-row block.
// B fragments (g_wp) prefetched 2 k-steps ahead in registers — no smem,
// no barrier dependence, pipelines across Xs tiles.
// grid = 256 (all SMs busy, 2-3 blocks/SM), 192 threads.
// ============================================================================
__global__ __launch_bounds__(192, 3) void qkv_tf32(const float* __restrict__ x) {
    __shared__ float Xs[2][32][36];

    const int tid  = threadIdx.x;
    const int lane = tid & 31;
    const int wid  = tid >> 5;
    const int mi   = wid >> 1;
    const int mrow = (wid & 1) * 16;
    const int g    = lane >> 2;
    const int tig  = lane & 3;
    const int m0   = blockIdx.x * 32;

    // x loader: 32x32 tile = 256 float4 over 192 threads (t<64 carry 2)
    const int r0 = tid >> 3,        c0 = (tid & 7) * 4;
    const bool has2 = (tid < 64);
    const int e1 = tid + 192;
    const int r1 = e1 >> 3,         c1 = (e1 & 7) * 4;

    float c[8][4];
#pragma unroll
    for (int nt = 0; nt < 8; ++nt)
#pragma unroll
        for (int i = 0; i < 4; ++i) c[nt][i] = 0.f;

    // preload x tile 0 into buffer 0
    {
        float4 p0 = *(const float4*)(x + (size_t)(m0 + r0) * EMB + c0);
        *(float4*)&Xs[0][r0][c0] =
            make_float4(to_tf32(p0.x), to_tf32(p0.y), to_tf32(p0.z), to_tf32(p0.w));
        if (has2) {
            float4 p1 = *(const float4*)(x + (size_t)(m0 + r1) * EMB + c1);
            *(float4*)&Xs[0][r1][c1] =
                make_float4(to_tf32(p1.x), to_tf32(p1.y), to_tf32(p1.z), to_tf32(p1.w));
        }
    }

    // B fragment pipeline: bfr[kk&1] holds fragment for k-step kk.
    const float4* wpbase = (const float4*)g_wp + (size_t)mi * 128 * 4 * 32 + lane;
    float4 bfr[2][4];
#pragma unroll
    for (int j = 0; j < 4; ++j) {
        bfr[0][j] = wpbase[0 * 128 + j * 32];   // kk = 0
        bfr[1][j] = wpbase[1 * 128 + j * 32];   // kk = 1
    }
    __syncthreads();

    for (int t = 0; t < EMB / 32; ++t) {
        const int cur = t & 1;
        const bool hn = (t + 1 < EMB / 32);

        float4 p0, p1;
        if (hn) {   // issue next x tile loads; consumed after compute
            const int kn = (t + 1) * 32;
            p0 = *(const float4*)(x + (size_t)(m0 + r0) * EMB + kn + c0);
            if (has2) p1 = *(const float4*)(x + (size_t)(m0 + r1) * EMB + kn + c1);
        }

#pragma unroll
        for (int ks = 0; ks < 4; ++ks) {
            const int kk = t * 4 + ks;
            const int kb = ks * 8;
            const float* bf = (const float*)bfr[kk & 1];

            unsigned int a0 = __float_as_uint(Xs[cur][mrow + g    ][kb + tig    ]);
            unsigned int a1 = __float_as_uint(Xs[cur][mrow + g + 8][kb + tig    ]);
            unsigned int a2 = __float_as_uint(Xs[cur][mrow + g    ][kb + tig + 4]);
            unsigned int a3 = __float_as_uint(Xs[cur][mrow + g + 8][kb + tig + 4]);
#pragma unroll
            for (int nt = 0; nt < 8; ++nt) {
                unsigned int b0 = __float_as_uint(bf[nt * 2]);
                unsigned int b1 = __float_as_uint(bf[nt * 2 + 1]);
                MMA_TF32(c[nt], a0, a1, a2, a3, b0, b1);
            }
            // prefetch kk+2 into the stage just consumed (WAR: safe post-issue)
            if (kk + 2 < 128) {
#pragma unroll
                for (int j = 0; j < 4; ++j)
                    bfr[kk & 1][j] = wpbase[(size_t)(kk + 2) * 128 + j * 32];
            }
        }

        if (hn) {   // store next x tile to other buffer
            const int nxt = cur ^ 1;
            *(float4*)&Xs[nxt][r0][c0] =
                make_float4(to_tf32(p0.x), to_tf32(p0.y), to_tf32(p0.z), to_tf32(p0.w));
            if (has2)
                *(float4*)&Xs[nxt][r1][c1] =
                    make_float4(to_tf32(p1.x), to_tf32(p1.y), to_tf32(p1.z), to_tf32(p1.w));
        }
        __syncthreads();   // one barrier per k0 tile
    }

    float* out = (mi == 0) ? g_q : (mi == 1 ? g_k : g_v);
    const int row0 = m0 + mrow + g;
#pragma unroll
    for (int nt = 0; nt < 8; ++nt) {
        const int col = nt * 8 + 2 * tig;
        *(float2*)&out[(size_t)row0       * HD + col] =
            make_float2(to_tf32(c[nt][0]), to_tf32(c[nt][1]));
        *(float2*)&out[(size_t)(row0 + 8) * HD + col] =
            make_float2(to_tf32(c[nt][2]), to_tf32(c[nt][3]));
    }
}

// ============================================================================
// Kernel 2: flash attention partial, 3-slot cp.async ring (unchanged).
// grid = (MAXCH, NQT, BATCH), 128 threads, 3 blocks/SM.
// ============================================================================
__global__ __launch_bounds__(128, 3) void attn_mma() {
    const int ch = blockIdx.x, qt = blockIdx.y, b = blockIdx.z;
    const int kstart = ch * KCH;
    const int kend   = min(kstart + KCH, (qt + 1) * TQ);
    if (kstart >= kend) return;

    extern __shared__ float sm[];
    float* Kb = sm;
    float* Vb = sm + KBUF_FLOATS;
    float* Pb = sm + KBUF_FLOATS + VBUF_FLOATS;
    const unsigned smem_k = (unsigned)__cvta_generic_to_shared(Kb);
    const unsigned smem_v = (unsigned)__cvta_generic_to_shared(Vb);

    const int tid  = threadIdx.x;
    const int lane = tid & 31;
    const int warp = tid >> 5;
    const int g    = lane >> 2;
    const int tig  = lane & 3;
    const int w16  = warp * 16;
    const int qw0  = qt * TQ + w16;

    int srow[4], scol[4];
#pragma unroll
    for (int i = 0; i < 4; ++i) {
        int e = i * 128 + tid;
        srow[i] = e >> 4; scol[i] = (e & 15) * 4;
    }
    const int nkt = (kend - kstart) / KT;

#pragma unroll
    for (int i = 0; i < 4; ++i) {
        const size_t gb = (size_t)(b * SEQ + kstart + srow[i]) * HD + scol[i];
        CP_ASYNC16(smem_k + (srow[i] * KSTR + scol[i]) * 4, g_k + gb);
        CP_ASYNC16(smem_v + (srow[i] * VSTR + scol[i]) * 4, g_v + gb);
    }
    CP_COMMIT();
    if (nkt > 1) {
#pragma unroll
        for (int i = 0; i < 4; ++i) {
            const size_t gb = (size_t)(b * SEQ + kstart + KT + srow[i]) * HD + scol[i];
            CP_ASYNC16(smem_k + ((KSLOT + srow[i] * KSTR + scol[i])) * 4, g_k + gb);
            CP_ASYNC16(smem_v + ((VSLOT + srow[i] * VSTR + scol[i])) * 4, g_v + gb);
        }
        CP_COMMIT();
    }

    float a[8][4];
    {
        const float* qb = g_q + (size_t)(b * SEQ + qw0) * HD;
        const float qs = SCALE * LOG2E;
#pragma unroll
        for (int ks = 0; ks < 8; ++ks) {
            a[ks][0] = qb[(size_t)g       * HD + ks * 8 + tig    ] * qs;
            a[ks][1] = qb[(size_t)(g + 8) * HD + ks * 8 + tig    ] * qs;
            a[ks][2] = qb[(size_t)g       * HD + ks * 8 + tig + 4] * qs;
            a[ks][3] = qb[(size_t)(g + 8) * HD + ks * 8 + tig + 4] * qs;
        }
    }

    float oc[8][4];
#pragma unroll
    for (int nt = 0; nt < 8; ++nt)
#pragma unroll
        for (int i = 0; i < 4; ++i) oc[nt][i] = 0.f;
    float m0r = -1e30f, m1r = -1e30f, l0 = 0.f, l1 = 0.f;

    int slot = 0;
    for (int t = 0; t < nkt; ++t) {
        const int kt0 = kstart + t * KT;
        float* Kc = Kb + slot * KSLOT;
        float* Vc = Vb + slot * VSLOT;

        if (t + 1 < nkt) { CP_WAIT1(); } else { CP_WAIT0(); }
        __syncthreads();

        if (t + 2 < nkt) {
            const int ps = (slot + 2) % 3;
#pragma unroll
            for (int i = 0; i < 4; ++i) {
                const size_t gb = (size_t)(b * SEQ + kt0 + 2 * KT + srow[i]) * HD + scol[i];
                CP_ASYNC16(smem_k + (ps * KSLOT + srow[i] * KSTR + scol[i]) * 4, g_k + gb);
                CP_ASYNC16(smem_v + (ps * VSLOT + srow[i] * VSTR + scol[i]) * 4, g_v + gb);
            }
            CP_COMMIT();
        }

        float s[4][4];
#pragma unroll
        for (int nt = 0; nt < 4; ++nt)
#pragma unroll
            for (int i = 0; i < 4; ++i) s[nt][i] = 0.f;
#pragma unroll
        for (int ks = 0; ks < 8; ++ks) {
            unsigned int a0 = __float_as_uint(a[ks][0]);
            unsigned int a1 = __float_as_uint(a[ks][1]);
            unsigned int a2 = __float_as_uint(a[ks][2]);
            unsigned int a3 = __float_as_uint(a[ks][3]);
#pragma unroll
            for (int nt = 0; nt < 4; ++nt) {
                unsigned int b0 = __float_as_uint(Kc[(nt * 8 + g) * KSTR + ks * 8 + tig    ]);
                unsigned int b1 = __float_as_uint(Kc[(nt * 8 + g) * KSTR + ks * 8 + tig + 4]);
                MMA_TF32(s[nt], a0, a1, a2, a3, b0, b1);
            }
        }

        if (kt0 + KT - 1 > qw0) {
#pragma unroll
            for (int nt = 0; nt < 4; ++nt) {
                const int col = kt0 + nt * 8 + 2 * tig;
                if (col     > qw0 + g)     s[nt][0] = -1e30f;
                if (col + 1 > qw0 + g)     s[nt][1] = -1e30f;
                if (col     > qw0 + g + 8) s[nt][2] = -1e30f;
                if (col + 1 > qw0 + g + 8) s[nt][3] = -1e30f;
            }
        }

        float mx0 = -1e30f, mx1 = -1e30f;
#pragma unroll
        for (int nt = 0; nt < 4; ++nt) {
            mx0 = fmaxf(mx0, fmaxf(s[nt][0], s[nt][1]));
            mx1 = fmaxf(mx1, fmaxf(s[nt][2], s[nt][3]));
        }
        mx0 = fmaxf(mx0, __shfl_xor_sync(0xffffffffu, mx0, 1));
        mx0 = fmaxf(mx0, __shfl_xor_sync(0xffffffffu, mx0, 2));
        mx1 = fmaxf(mx1, __shfl_xor_sync(0xffffffffu, mx1, 1));
        mx1 = fmaxf(mx1, __shfl_xor_sync(0xffffffffu, mx1, 2));

        const float mn0 = fmaxf(m0r, mx0), mn1 = fmaxf(m1r, mx1);
        const float corr0 = exp2f(m0r - mn0), corr1 = exp2f(m1r - mn1);

        float sum0 = 0.f, sum1 = 0.f;
#pragma unroll
        for (int nt = 0; nt < 4; ++nt) {
            float p0 = to_tf32(exp2f(s[nt][0] - mn0));
            float p1 = to_tf32(exp2f(s[nt][1] - mn0));
            float p2 = to_tf32(exp2f(s[nt][2] - mn1));
            float p3 = to_tf32(exp2f(s[nt][3] - mn1));
            sum0 += p0 + p1;
            sum1 += p2 + p3;
            *(float2*)&Pb[(w16 + g    ) * PSTR + nt * 8 + 2 * tig] = make_float2(p0, p1);
            *(float2*)&Pb[(w16 + g + 8) * PSTR + nt * 8 + 2 * tig] = make_float2(p2, p3);
        }
        sum0 += __shfl_xor_sync(0xffffffffu, sum0, 1);
        sum0 += __shfl_xor_sync(0xffffffffu, sum0, 2);
        sum1 += __shfl_xor_sync(0xffffffffu, sum1, 1);
        sum1 += __shfl_xor_sync(0xffffffffu, sum1, 2);

        l0 = l0 * corr0 + sum0;
        l1 = l1 * corr1 + sum1;
        m0r = mn0; m1r = mn1;
#pragma unroll
        for (int nt = 0; nt < 8; ++nt) {
            oc[nt][0] *= corr0; oc[nt][1] *= corr0;
            oc[nt][2] *= corr1; oc[nt][3] *= corr1;
        }
        __syncwarp();

#pragma unroll
        for (int ks = 0; ks < 4; ++ks) {
            unsigned int p0 = __float_as_uint(Pb[(w16 + g    ) * PSTR + ks * 8 + tig    ]);
            unsigned int p1 = __float_as_uint(Pb[(w16 + g + 8) * PSTR + ks * 8 + tig    ]);
            unsigned int p2 = __float_as_uint(Pb[(w16 + g    ) * PSTR + ks * 8 + tig + 4]);
            unsigned int p3 = __float_as_uint(Pb[(w16 + g + 8) * PSTR + ks * 8 + tig + 4]);
#pragma unroll
            for (int nt = 0; nt < 8; ++nt) {
                unsigned int b0 = __float_as_uint(Vc[(ks * 8 + tig    ) * VSTR + nt * 8 + g]);
                unsigned int b1 = __float_as_uint(Vc[(ks * 8 + tig + 4) * VSTR + nt * 8 + g]);
                MMA_TF32(oc[nt], p0, p1, p2, p3, b0, b1);
            }
        }
        slot = (slot + 1) % 3;
    }

    const int part = (b * NQT + qt) * MAXCH + ch;
    float* po = g_po + (size_t)part * TQ * HD;
#pragma unroll
    for (int nt = 0; nt < 8; ++nt) {
        const int col = nt * 8 + 2 * tig;
        *(float2*)&po[(size_t)(w16 + g)     * HD + col] = make_float2(oc[nt][0], oc[nt][1]);
        *(float2*)&po[(size_t)(w16 + g + 8) * HD + col] = make_float2(oc[nt][2], oc[nt][3]);
    }
    g_pm[part * TQ + w16 + g]     = m0r;
    g_pm[part * TQ + w16 + g + 8] = m1r;
    g_pl[part * TQ + w16 + g]     = l0;
    g_pl[part * TQ + w16 + g + 8] = l1;
}

// ============================================================================
// Kernel 3: combine — one thread per float4 of output (unchanged).
// ============================================================================
__global__ __launch_bounds__(256) void attn_combine(float* __restrict__ out) {
    const int idx = blockIdx.x * 256 + threadIdx.x;
    const int d4  = (idx & 15) * 4;
    const int row = idx >> 4;
    const int b   = row >> 11;
    const int qr  = row & (SEQ - 1);
    const int qt  = qr >> 6;
    const int rin = qr & (TQ - 1);
    const int nch = (qt + 4) >> 2;
    const int pbase = (b * NQT + qt) * MAXCH;

    float M = -1e30f;
#pragma unroll 4
    for (int c = 0; c < nch; ++c)
        M = fmaxf(M, g_pm[(pbase + c) * TQ + rin]);

    float L = 0.f;
    float4 o = make_float4(0.f, 0.f, 0.f, 0.f);
#pragma unroll 4
    for (int c = 0; c < nch; ++c) {
        const int part = pbase + c;
        const float w = exp2f(g_pm[part * TQ + rin] - M);
        L += g_pl[part * TQ + rin] * w;
        float4 v = *(const float4*)(g_po + ((size_t)part * TQ + rin) * HD + d4);
        o.x += w * v.x; o.y += w * v.y; o.z += w * v.z; o.w += w * v.w;
    }
    const float inv = 1.f / L;
    *(float4*)(out + (size_t)row * HD + d4) =
        make_float4(o.x * inv, o.y * inv, o.z * inv, o.w * inv);
}

// ============================================================================
// Launch
// ============================================================================
extern "C" void kernel_launch(void* const* d_in, const int* in_sizes, int n_in,
                              void* d_out, int out_size) {
    (void)in_sizes; (void)n_in; (void)out_size;
    const float* x  = (const float*)d_in[0];
    const float* Wq = (const float*)d_in[1];
    const float* Wk = (const float*)d_in[2];
    const float* Wv = (const float*)d_in[3];
    float* out = (float*)d_out;

    static int smem_set = 0;
    if (!smem_set) {
        cudaFuncSetAttribute(attn_mma, cudaFuncAttributeMaxDynamicSharedMemorySize,
                             ATTN_SMEM_BYTES);
        smem_set = 1;
    }

    prepack     <<<24, 256>>>(Wq, Wk, Wv);
    ncu_shift   <<<1, 32>>>();   // align ncu -s 5 capture onto qkv_tf32
    ncu_shift   <<<1, 32>>>();
    qkv_tf32    <<<ROWS / 32, 192>>>(x);
    attn_mma    <<<dim3(MAXCH, NQT, BATCH), 128, ATTN_SMEM_BYTES>>>();
    attn_combine<<<(ROWS * HD / 4) / 256, 256>>>(out);
}